// round 13
// baseline (speedup 1.0000x reference)
#include <cuda_runtime.h>

// Problem constants
#define Bn     32
#define Cn     40
#define Ln     16000
#define Kn     128
#define Sn     125      // LS / STRIDE
#define STILE  32       // s-values per block
#define NTILES 4        // ceil(125/32)
#define NOUT   (Bn * Cn * Sn)   // 160000 outputs (real part)

#define XSEG   132               // 128 data + 4 pad floats per segment

// ---- packed f32x2 helpers (Blackwell sm_103a) ----
#define FMA2(acc, a, b) \
    asm("fma.rn.f32x2 %0, %1, %2, %0;" : "+l"(acc) : "l"(a), "l"(b))
#define ADD2(acc, a) \
    asm("add.rn.f32x2 %0, %0, %1;" : "+l"(acc) : "l"(a))
#define PACKDUP(out, f) \
    asm("mov.b64 %0, {%1, %1};" : "=l"(out) : "f"(f))
#define UNPACK2(lo, hi, in) \
    asm("mov.b64 {%0, %1}, %2;" : "=f"(lo), "=f"(hi) : "l"(in))

// ---------------- fast mode-0 kernel (real part only) ----------------
// Grid (4 stiles, 32 b, 4 cg) = 512 blocks x 256 threads (8 warps).
// Block: channel-group cg -> 5 channel PAIRS (10 channels), 32 s-values.
//   warp w  -> s-quad (4 s-values): s = stile*32 + w*4 + si
//   lane    -> q = lane>>2 (16-tap K-slice, 8 slices), si = lane&3
// K-slice reduction in-warp via 3 shfl.bfly (lane bits 2..4); lanes q<5
// write pair cg*5+q. No partials smem, single barrier.
//
// smem (static, 22656 B -> ~5 CTAs/SM resident):
//   kp : 5 pairs x [8 slices x 18 float2] (16 taps + 2 pad per slice so the
//        8 per-warp kernel addresses land on disjoint 4-bank groups)
//        kp[p][m] = (kr[2P][127-m], kr[2P+1][127-m]), P = cg*5+p,
//        at f2 idx p*144 + (m>>4)*18 + (m&15)
//   xs : 32 segments x 132 floats (optimal 4-phase float4 LDS)
#define KP_F2     (5 * 144)            // 720 float2 = 1440 floats
#define XS_FLOATS (32 * XSEG)          // 4224
#define SMF_FAST  (2 * KP_F2 + XS_FLOATS)   // 5664 floats = 22656 B

__global__ __launch_bounds__(256, 5)
void isac_conv_fast(const float* __restrict__ x,
                    const float* __restrict__ kr,
                    float* __restrict__ out)
{
    __shared__ float sm[SMF_FAST];
    float2* kp = (float2*)sm;
    float*  xs = sm + 2 * KP_F2;

    const int tid   = threadIdx.x;
    const int stile = blockIdx.x;
    const int b     = blockIdx.y;
    const int cg    = blockIdx.z;      // channel-pair group (5 pairs)

    // ---- x tile: segment L holds x[128*(s0+L)-127 .. 128*(s0+L)] ----
    const int gstart = stile * (STILE * Kn) - 127;   // negative only for tile 0
    const float* xb = x + b * Ln;
    #pragma unroll
    for (int i = 0; i < 16; i++) {
        const int j = tid + i * 256;   // j in [0, 4096)
        int g = gstart + j;
        if (g < 0)        g += Ln;
        else if (g >= Ln) g -= Ln;
        xs[(j >> 7) * XSEG + (j & 127)] = xb[g];
    }

    // ---- kernel repack: 5 pairs, tap-reversed, slice-padded ----
    #pragma unroll
    for (int i = 0; i < 3; i++) {
        const int idx = tid + i * 256;
        if (idx < 640) {               // 5 pairs x 128 taps
            const int p = idx >> 7, m = idx & 127;
            const int P = cg * 5 + p;
            kp[p * 144 + (m >> 4) * 18 + (m & 15)] =
                make_float2(kr[(2 * P)     * Kn + (127 - m)],
                            kr[(2 * P + 1) * Kn + (127 - m)]);
        }
    }
    __syncthreads();

    // ---- compute: 5 pairs x 16-tap slice, one s per thread ----
    const int lane = tid & 31;
    const int w    = tid >> 5;
    const int q    = lane >> 2;        // K slice (16 taps)
    const int si   = lane & 3;         // s within quad
    const int sl   = w * 4 + si;       // s within 32-s tile

    const float4* xp = (const float4*)(xs + sl * XSEG + q * 16);
    // ull2 units: pair stride 72, slice stride 9
    const ulonglong2* kb = (const ulonglong2*)kp + q * 9;

    unsigned long long acc[5] = {0ull, 0ull, 0ull, 0ull, 0ull};

    #pragma unroll
    for (int i = 0; i < 4; i++) {      // 4 float4 = 16 taps
        const float4 xv = xp[i];
        unsigned long long x0, x1, x2, x3;
        PACKDUP(x0, xv.x); PACKDUP(x1, xv.y);
        PACKDUP(x2, xv.z); PACKDUP(x3, xv.w);
        #pragma unroll
        for (int j = 0; j < 5; j++) {
            const ulonglong2 k01 = kb[j * 72 + 2 * i];      // taps 4i,4i+1
            const ulonglong2 k23 = kb[j * 72 + 2 * i + 1];  // taps 4i+2,4i+3
            FMA2(acc[j], x0, k01.x);
            FMA2(acc[j], x1, k01.y);
            FMA2(acc[j], x2, k23.x);
            FMA2(acc[j], x3, k23.y);
        }
    }

    // ---- in-warp K-slice reduction: bfly over lane bits 2..4 ----
    #pragma unroll
    for (int mask = 4; mask <= 16; mask <<= 1) {
        #pragma unroll
        for (int j = 0; j < 5; j++) {
            const unsigned long long o =
                __shfl_xor_sync(0xffffffffu, acc[j], mask);
            ADD2(acc[j], o);
        }
    }

    // ---- write: lanes q<5 write pair cg*5+q for their s ----
    if (q < 5) {
        unsigned long long v;
        switch (q) {
            case 0:  v = acc[0]; break;
            case 1:  v = acc[1]; break;
            case 2:  v = acc[2]; break;
            case 3:  v = acc[3]; break;
            default: v = acc[4]; break;
        }
        float lo, hi;
        UNPACK2(lo, hi, v);
        const int P = cg * 5 + q;
        const int s = stile * STILE + sl;
        if (s < Sn) {
            out[(b * Cn + 2 * P)     * Sn + s] = lo;
            out[(b * Cn + 2 * P + 1) * Sn + s] = hi;
        }
    }
}

// ---------------- fallback (full complex) — not expected to trigger ----------------
#define KERN_FLOATS (Cn * Kn)
#define SMEMB_FB ((2 * KERN_FLOATS + 32 * XSEG) * 4)

__global__ __launch_bounds__(256)
void isac_conv_fallback(const float* __restrict__ x,
                        const float* __restrict__ kr,
                        const float* __restrict__ ki,
                        float* __restrict__ out,
                        int mode)   // 1 = planar, 2 = interleaved
{
    extern __shared__ float smem[];
    float* kr_s = smem;
    float* ki_s = smem + KERN_FLOATS;
    float* xs   = smem + 2 * KERN_FLOATS;

    const int tid = threadIdx.x, stile = blockIdx.x, b = blockIdx.y;
    #pragma unroll 4
    for (int idx = tid; idx < KERN_FLOATS; idx += 256) {
        const int c = idx >> 7, m = idx & 127;
        kr_s[idx] = kr[c * Kn + (127 - m)];
        ki_s[idx] = ki[c * Kn + (127 - m)];
    }
    const int gstart = stile * (STILE * Kn) - 127;
    const float* xb = x + b * Ln;
    #pragma unroll 4
    for (int j = tid; j < 32 * Kn; j += 256) {
        int g = gstart + j;
        if (g < 0) g += Ln; else if (g >= Ln) g -= Ln;
        xs[(j >> 7) * XSEG + (j & 127)] = xb[g];
    }
    __syncthreads();

    const int lane = tid & 31, w = tid >> 5;
    const int s = stile * STILE + lane, c0 = w * 5;
    const float4* xp  = (const float4*)(xs + lane * XSEG);
    const float4* krp = (const float4*)(kr_s + c0 * Kn);
    const float4* kip = (const float4*)(ki_s + c0 * Kn);

    float ar[5] = {0,0,0,0,0}, ai[5] = {0,0,0,0,0};
    #pragma unroll 2
    for (int m4 = 0; m4 < Kn / 4; m4++) {
        const float4 xv = xp[m4];
        #pragma unroll
        for (int cc = 0; cc < 5; cc++) {
            const float4 kv = krp[cc * (Kn / 4) + m4];
            const float4 iv = kip[cc * (Kn / 4) + m4];
            ar[cc] = fmaf(xv.x, kv.x, fmaf(xv.y, kv.y, fmaf(xv.z, kv.z, fmaf(xv.w, kv.w, ar[cc]))));
            ai[cc] = fmaf(xv.x, iv.x, fmaf(xv.y, iv.y, fmaf(xv.z, iv.z, fmaf(xv.w, iv.w, ai[cc]))));
        }
    }
    if (s < Sn) {
        if (mode == 1) {
            #pragma unroll
            for (int cc = 0; cc < 5; cc++) {
                const int idx = (b * Cn + (c0 + cc)) * Sn + s;
                out[idx] = ar[cc]; out[NOUT + idx] = ai[cc];
            }
        } else {
            float2* o2 = (float2*)out;
            #pragma unroll
            for (int cc = 0; cc < 5; cc++)
                o2[(b * Cn + (c0 + cc)) * Sn + s] = make_float2(ar[cc], ai[cc]);
        }
    }
}

extern "C" void kernel_launch(void* const* d_in, const int* in_sizes, int n_in,
                              void* d_out, int out_size)
{
    const float* x  = (const float*)d_in[0];   // (32, 1, 16000) f32
    const float* kr = (const float*)d_in[1];   // (40, 128) f32
    const float* ki = (const float*)d_in[2];   // (40, 128) f32
    float* out = (float*)d_out;

    if (out_size == NOUT) {
        dim3 grid(NTILES, Bn, 4);
        isac_conv_fast<<<grid, 256>>>(x, kr, out);
    } else {
        const int mode = (out_size == 2 * NOUT) ? 1 : 2;
        cudaFuncSetAttribute(isac_conv_fallback,
                             cudaFuncAttributeMaxDynamicSharedMemorySize, SMEMB_FB);
        dim3 grid(NTILES, Bn);
        isac_conv_fallback<<<grid, 256, SMEMB_FB>>>(x, kr, ki, out, mode);
    }
}

// round 14
// speedup vs baseline: 1.0331x; 1.0331x over previous
#include <cuda_runtime.h>

// Problem constants
#define Bn     32
#define Cn     40
#define Ln     16000
#define Kn     128
#define Sn     125      // LS / STRIDE
#define STILE  32       // s-values per block
#define NTILES 4        // ceil(125/32)
#define NOUT   (Bn * Cn * Sn)   // 160000 outputs (real part)

// ---- packed f32x2 helpers (Blackwell sm_103a) ----
#define FMA2(acc, a, b) \
    asm("fma.rn.f32x2 %0, %1, %2, %0;" : "+l"(acc) : "l"(a), "l"(b))
#define ADD2(acc, a) \
    asm("add.rn.f32x2 %0, %0, %1;" : "+l"(acc) : "l"(a))
#define UNPACK2(lo, hi, in) \
    asm("mov.b64 {%0, %1}, %2;" : "=f"(lo), "=f"(hi) : "l"(in))

// ---------------- fast mode-0 kernel (real part only) ----------------
// Grid (4, 32), 512 threads = 16 warps, one CTA per SM (single wave).
//   warp w: pg = w&3  (5 channel PAIRS = 10 channels), sq = w>>2 (8 s-values)
//   lane:   q = lane>>2 (16-tap K-slice, 8 slices), d = lane&3
//   thread covers TWO s: s_a = sq*8 + d*2, s_b = s_a + 1 (within 32-s tile)
// In-warp K-slice reduction via 3 shfl.bfly over lane bits 2..4.
//
// smem layout (f32x2 "pair" units of 8 B, q-slice padded so every LDS.128
// phase hits 8 distinct 16B bank groups: q stride 18 pairs = 144B = 16 mod 128,
// segment stride 146 pairs = 1168B = 16 mod 128):
//   xdup[sl][m] = (tile[128*sl+m], same)    sl<32, m<128   32*146 pairs
//   kp[P][m]    = (kr[2P][127-m], kr[2P+1][127-m])  P<20   20*146 pairs
//   where entry (seg, m) lives at seg*146 + (m>>4)*18 + (m&15)
#define XD_PAIRS  (32 * 146)           // 4672
#define KP_PAIRS  (20 * 146)           // 2920
#define SMEMB_FAST ((XD_PAIRS + KP_PAIRS) * 8)   // 60736 B (dynamic, opt-in)

__global__ __launch_bounds__(512, 1)
void isac_conv_fast(const float* __restrict__ x,
                    const float* __restrict__ kr,
                    float* __restrict__ out)
{
    extern __shared__ float2 smp[];
    float2* xdup = smp;
    float2* kp   = smp + XD_PAIRS;

    const int tid   = threadIdx.x;
    const int stile = blockIdx.x;
    const int b     = blockIdx.y;

    // ---- x tile, pre-duplicated: tile[j] = x[(g0+j) mod L] ----
    const int g0 = stile * (STILE * Kn) - 127;   // negative only for tile 0
    const float* xb = x + b * Ln;
    #pragma unroll
    for (int k = 0; k < 8; k++) {
        const int idx = tid + k * 512;           // 128*sl + m, idx < 4096
        int g = g0 + idx;
        if (g < 0)        g += Ln;
        else if (g >= Ln) g -= Ln;
        const float v = xb[g];
        const int sl = idx >> 7, m = idx & 127;
        xdup[sl * 146 + (m >> 4) * 18 + (m & 15)] = make_float2(v, v);
    }

    // ---- kernel channel-pairs, tap-reversed ----
    #pragma unroll
    for (int k = 0; k < 5; k++) {
        const int idx = tid + k * 512;           // 128*P + m, idx < 2560
        const int P = idx >> 7, m = idx & 127;
        kp[P * 146 + (m >> 4) * 18 + (m & 15)] =
            make_float2(kr[(2 * P)     * Kn + (127 - m)],
                        kr[(2 * P + 1) * Kn + (127 - m)]);
    }
    __syncthreads();

    // ---- compute: 2 s x 5 pairs x 16-tap slice per thread ----
    const int lane = tid & 31;
    const int w    = tid >> 5;
    const int pg   = w & 3;                // channel-pair group (5 pairs)
    const int sq   = w >> 2;               // 8-s group
    const int q    = lane >> 2;            // K slice (16 taps)
    const int d    = lane & 3;
    const int s_a  = sq * 8 + d * 2;       // s within 32-s tile
    // ulonglong2 units (2 pairs = 16B): stride per segment = 73, per q = 9
    const ulonglong2* xa = (const ulonglong2*)xdup + (s_a * 73 + q * 9);
    const ulonglong2* xbp = xa + 73;       // s_b = s_a + 1
    const ulonglong2* kb = (const ulonglong2*)kp + (pg * 5) * 73 + q * 9;

    unsigned long long accA[5] = {0,0,0,0,0};   // (ch 2P, ch 2P+1) at s_a
    unsigned long long accB[5] = {0,0,0,0,0};   // at s_b

    #pragma unroll
    for (int i = 0; i < 8; i++) {          // 2 taps per iteration
        const ulonglong2 va = xa[i];       // (dup x[s_a,t0], dup x[s_a,t1])
        const ulonglong2 vb = xbp[i];
        #pragma unroll
        for (int j = 0; j < 5; j++) {
            const ulonglong2 kv = kb[j * 73 + i];   // (pair t0, pair t1)
            FMA2(accA[j], va.x, kv.x);
            FMA2(accA[j], va.y, kv.y);
            FMA2(accB[j], vb.x, kv.x);
            FMA2(accB[j], vb.y, kv.y);
        }
    }

    // ---- in-warp K-slice reduction: bfly over lane bits 2..4 ----
    #pragma unroll
    for (int mask = 4; mask <= 16; mask <<= 1) {
        #pragma unroll
        for (int j = 0; j < 5; j++) {
            unsigned long long oA = __shfl_xor_sync(0xffffffffu, accA[j], mask);
            unsigned long long oB = __shfl_xor_sync(0xffffffffu, accB[j], mask);
            ADD2(accA[j], oA);
            ADD2(accB[j], oB);
        }
    }

    // ---- write: lanes q<5 write channel pair pg*5+q for (s_a, s_b) ----
    if (q < 5) {
        unsigned long long vA, vB;
        switch (q) {
            case 0:  vA = accA[0]; vB = accB[0]; break;
            case 1:  vA = accA[1]; vB = accB[1]; break;
            case 2:  vA = accA[2]; vB = accB[2]; break;
            case 3:  vA = accA[3]; vB = accB[3]; break;
            default: vA = accA[4]; vB = accB[4]; break;
        }
        float a0, a1, b0, b1;
        UNPACK2(a0, a1, vA);   // (ch 2P, 2P+1) at s_a
        UNPACK2(b0, b1, vB);   // at s_b
        const int P  = pg * 5 + q;
        const int sA = stile * STILE + s_a;
        const int sB = sA + 1;
        float* r0 = out + (b * Cn + 2 * P)     * Sn;
        float* r1 = out + (b * Cn + 2 * P + 1) * Sn;
        if (sA < Sn) { r0[sA] = a0; r1[sA] = a1; }
        if (sB < Sn) { r0[sB] = b0; r1[sB] = b1; }
    }
}

// ---------------- fallback (full complex) — not expected to trigger ----------------
#define XSEG        132
#define KERN_FLOATS (Cn * Kn)
#define SMEMB_FB ((2 * KERN_FLOATS + 32 * XSEG) * 4)

__global__ __launch_bounds__(256)
void isac_conv_fallback(const float* __restrict__ x,
                        const float* __restrict__ kr,
                        const float* __restrict__ ki,
                        float* __restrict__ out,
                        int mode)   // 1 = planar, 2 = interleaved
{
    extern __shared__ float smem[];
    float* kr_s = smem;
    float* ki_s = smem + KERN_FLOATS;
    float* xs   = smem + 2 * KERN_FLOATS;

    const int tid = threadIdx.x, stile = blockIdx.x, b = blockIdx.y;
    #pragma unroll 4
    for (int idx = tid; idx < KERN_FLOATS; idx += 256) {
        const int c = idx >> 7, m = idx & 127;
        kr_s[idx] = kr[c * Kn + (127 - m)];
        ki_s[idx] = ki[c * Kn + (127 - m)];
    }
    const int gstart = stile * (STILE * Kn) - 127;
    const float* xb = x + b * Ln;
    #pragma unroll 4
    for (int j = tid; j < 32 * Kn; j += 256) {
        int g = gstart + j;
        if (g < 0) g += Ln; else if (g >= Ln) g -= Ln;
        xs[(j >> 7) * XSEG + (j & 127)] = xb[g];
    }
    __syncthreads();

    const int lane = tid & 31, w = tid >> 5;
    const int s = stile * STILE + lane, c0 = w * 5;
    const float4* xp  = (const float4*)(xs + lane * XSEG);
    const float4* krp = (const float4*)(kr_s + c0 * Kn);
    const float4* kip = (const float4*)(ki_s + c0 * Kn);

    float ar[5] = {0,0,0,0,0}, ai[5] = {0,0,0,0,0};
    #pragma unroll 2
    for (int m4 = 0; m4 < Kn / 4; m4++) {
        const float4 xv = xp[m4];
        #pragma unroll
        for (int cc = 0; cc < 5; cc++) {
            const float4 kv = krp[cc * (Kn / 4) + m4];
            const float4 iv = kip[cc * (Kn / 4) + m4];
            ar[cc] = fmaf(xv.x, kv.x, fmaf(xv.y, kv.y, fmaf(xv.z, kv.z, fmaf(xv.w, kv.w, ar[cc]))));
            ai[cc] = fmaf(xv.x, iv.x, fmaf(xv.y, iv.y, fmaf(xv.z, iv.z, fmaf(xv.w, iv.w, ai[cc]))));
        }
    }
    if (s < Sn) {
        if (mode == 1) {
            #pragma unroll
            for (int cc = 0; cc < 5; cc++) {
                const int idx = (b * Cn + (c0 + cc)) * Sn + s;
                out[idx] = ar[cc]; out[NOUT + idx] = ai[cc];
            }
        } else {
            float2* o2 = (float2*)out;
            #pragma unroll
            for (int cc = 0; cc < 5; cc++)
                o2[(b * Cn + (c0 + cc)) * Sn + s] = make_float2(ar[cc], ai[cc]);
        }
    }
}

extern "C" void kernel_launch(void* const* d_in, const int* in_sizes, int n_in,
                              void* d_out, int out_size)
{
    const float* x  = (const float*)d_in[0];   // (32, 1, 16000) f32
    const float* kr = (const float*)d_in[1];   // (40, 128) f32
    const float* ki = (const float*)d_in[2];   // (40, 128) f32
    float* out = (float*)d_out;

    if (out_size == NOUT) {
        cudaFuncSetAttribute(isac_conv_fast,
                             cudaFuncAttributeMaxDynamicSharedMemorySize, SMEMB_FAST);
        dim3 grid(NTILES, Bn);
        isac_conv_fast<<<grid, 512, SMEMB_FAST>>>(x, kr, out);
    } else {
        const int mode = (out_size == 2 * NOUT) ? 1 : 2;
        cudaFuncSetAttribute(isac_conv_fallback,
                             cudaFuncAttributeMaxDynamicSharedMemorySize, SMEMB_FB);
        dim3 grid(NTILES, Bn);
        isac_conv_fallback<<<grid, 256, SMEMB_FB>>>(x, kr, ki, out, mode);
    }
}